// round 1
// baseline (speedup 1.0000x reference)
#include <cuda_runtime.h>
#include <cuda_bf16.h>
#include <math.h>

// Problem constants
#define Bn   256
#define In   256
#define Hn   512
#define An   400
#define Vn   50000
#define OOVn 50
#define Pn   (Vn + OOVn)      // 50050
#define H2   (2 * Hn)          // 1024 (fc1 out / fc2 K)
#define DIN  (An + Hn)         // 912

// Scratch (static device globals: allocation-free rule)
__device__ float g_h[Bn * Hn];
__device__ float g_att[Bn * An];
__device__ float g_ctxp[4 * Bn * An];
__device__ float g_ctx[Bn * An];
__device__ float g_fc1[Bn * H2];
__device__ float g_gen[Bn];
__device__ float g_sum[Bn];
__device__ float g_exp[(size_t)Bn * Vn];   // 51.2 MB

__device__ __forceinline__ float sigmoidf(float x) { return 1.0f / (1.0f + expf(-x)); }

__device__ __forceinline__ float warp_sum(float v) {
    #pragma unroll
    for (int o = 16; o; o >>= 1) v += __shfl_xor_sync(0xFFFFFFFFu, v, o);
    return v;
}

__device__ __forceinline__ float block_sum(float v, float* red) {
    int lane = threadIdx.x & 31, warp = threadIdx.x >> 5;
    v = warp_sum(v);
    if (lane == 0) red[warp] = v;
    __syncthreads();
    int nw = (blockDim.x + 31) >> 5;
    float r = (threadIdx.x < nw) ? red[threadIdx.x] : 0.0f;
    if (warp == 0) r = warp_sum(r);
    if (threadIdx.x == 0) red[0] = r;
    __syncthreads();
    return red[0];
}

__device__ __forceinline__ float block_max(float v, float* red) {
    int lane = threadIdx.x & 31, warp = threadIdx.x >> 5;
    #pragma unroll
    for (int o = 16; o; o >>= 1) v = fmaxf(v, __shfl_xor_sync(0xFFFFFFFFu, v, o));
    if (lane == 0) red[warp] = v;
    __syncthreads();
    int nw = (blockDim.x + 31) >> 5;
    float r = (threadIdx.x < nw) ? red[threadIdx.x] : -INFINITY;
    if (warp == 0) {
        #pragma unroll
        for (int o = 16; o; o >>= 1) r = fmaxf(r, __shfl_xor_sync(0xFFFFFFFFu, r, o));
    }
    if (threadIdx.x == 0) red[0] = r;
    __syncthreads();
    return red[0];
}

// ---------------------------------------------------------------------------
// K1: degenerate LSTM cell (no recurrent term, no f-gate used)
// gates = x0 @ W_ih.T + b_ih + b_hh ; c = sig(i)*tanh(g) ; h = sig(o)*tanh(c)
// ---------------------------------------------------------------------------
__global__ void k_lstm(const float* __restrict__ x, const float* __restrict__ W_ih,
                       const float* __restrict__ b_ih, const float* __restrict__ b_hh) {
    int b = blockIdx.x;
    __shared__ float sx[In];
    for (int i = threadIdx.x; i < In; i += blockDim.x) sx[i] = x[b * In + i];
    __syncthreads();
    int warp = threadIdx.x >> 5, lane = threadIdx.x & 31;
    for (int j = warp; j < Hn; j += (blockDim.x >> 5)) {
        const float* wi = W_ih + (size_t)j * In;
        const float* wg = W_ih + (size_t)(2 * Hn + j) * In;
        const float* wo = W_ih + (size_t)(3 * Hn + j) * In;
        float ai = 0.f, ag = 0.f, ao = 0.f;
        for (int k = lane; k < In; k += 32) {
            float xv = sx[k];
            ai = fmaf(xv, wi[k], ai);
            ag = fmaf(xv, wg[k], ag);
            ao = fmaf(xv, wo[k], ao);
        }
        ai = warp_sum(ai); ag = warp_sum(ag); ao = warp_sum(ao);
        if (lane == 0) {
            ai += b_ih[j] + b_hh[j];
            ag += b_ih[2 * Hn + j] + b_hh[2 * Hn + j];
            ao += b_ih[3 * Hn + j] + b_hh[3 * Hn + j];
            float c = sigmoidf(ai) * tanhf(ag);
            g_h[b * Hn + j] = sigmoidf(ao) * tanhf(c);
        }
    }
}

// ---------------------------------------------------------------------------
// K2: e = tanh(enc_state @ Wh.T + Wh_b + h @ Ws.T + Ws_b); att = v * softmax(e)
// ---------------------------------------------------------------------------
__global__ void k_attn(const float* __restrict__ enc_state,
                       const float* __restrict__ Wh_w, const float* __restrict__ Wh_b,
                       const float* __restrict__ Ws_w, const float* __restrict__ Ws_b,
                       const float* __restrict__ vvec) {
    int b = blockIdx.x;
    __shared__ float ss[Hn], sh[Hn], se[An], red[32];
    for (int i = threadIdx.x; i < Hn; i += blockDim.x) {
        ss[i] = enc_state[b * Hn + i];
        sh[i] = g_h[b * Hn + i];
    }
    __syncthreads();
    int warp = threadIdx.x >> 5, lane = threadIdx.x & 31;
    for (int a = warp; a < An; a += (blockDim.x >> 5)) {
        const float* w1 = Wh_w + (size_t)a * Hn;
        const float* w2 = Ws_w + (size_t)a * Hn;
        float acc = 0.f;
        for (int k = lane; k < Hn; k += 32)
            acc = fmaf(ss[k], w1[k], fmaf(sh[k], w2[k], acc));
        acc = warp_sum(acc);
        if (lane == 0) se[a] = tanhf(acc + Wh_b[a] + Ws_b[a]);
    }
    __syncthreads();
    float m = -INFINITY;
    for (int i = threadIdx.x; i < An; i += blockDim.x) m = fmaxf(m, se[i]);
    m = block_max(m, red);
    float s = 0.f;
    for (int i = threadIdx.x; i < An; i += blockDim.x) s += expf(se[i] - m);
    s = block_sum(s, red);
    float inv = 1.0f / s;
    for (int i = threadIdx.x; i < An; i += blockDim.x)
        g_att[b * An + i] = vvec[i] * expf(se[i] - m) * inv;
}

// ---------------------------------------------------------------------------
// K3: context partials: ctxp[s][b][e] = sum_{a in slice s} att[b,a]*enc[b,a,e]
// ---------------------------------------------------------------------------
__global__ void k_ctx(const float* __restrict__ enc_out) {
    int slice = blockIdx.x;     // 0..3
    int b = blockIdx.y;         // 0..255
    int a0 = slice * 100;
    __shared__ float sa[100];
    if (threadIdx.x < 100) sa[threadIdx.x] = g_att[b * An + a0 + threadIdx.x];
    __syncthreads();
    int e = threadIdx.x;
    if (e < An) {
        const float* base = enc_out + ((size_t)b * An + a0) * An + e;
        float acc = 0.f;
        #pragma unroll 5
        for (int i = 0; i < 100; i++) acc = fmaf(sa[i], base[(size_t)i * An], acc);
        g_ctxp[((size_t)slice * Bn + b) * An + e] = acc;
    }
}

__global__ void k_ctxred() {
    int b = blockIdx.x;
    int e = threadIdx.x;
    if (e < An) {
        float s = g_ctxp[((size_t)0 * Bn + b) * An + e]
                + g_ctxp[((size_t)1 * Bn + b) * An + e]
                + g_ctxp[((size_t)2 * Bn + b) * An + e]
                + g_ctxp[((size_t)3 * Bn + b) * An + e];
        g_ctx[b * An + e] = s;
    }
}

// ---------------------------------------------------------------------------
// K4: fc1_out = [context, h] @ fc1_w.T + fc1_b
// ---------------------------------------------------------------------------
__global__ void k_fc1(const float* __restrict__ fc1_w, const float* __restrict__ fc1_b) {
    int b = blockIdx.x;
    __shared__ float sd[DIN];
    for (int i = threadIdx.x; i < An; i += blockDim.x) sd[i] = g_ctx[b * An + i];
    for (int i = threadIdx.x; i < Hn; i += blockDim.x) sd[An + i] = g_h[b * Hn + i];
    __syncthreads();
    int warp = threadIdx.x >> 5, lane = threadIdx.x & 31;
    for (int j = warp; j < H2; j += (blockDim.x >> 5)) {
        const float* w = fc1_w + (size_t)j * DIN;
        float acc = 0.f;
        for (int k = lane; k < DIN; k += 32) acc = fmaf(sd[k], w[k], acc);
        acc = warp_sum(acc);
        if (lane == 0) g_fc1[b * H2 + j] = acc + fc1_b[j];
    }
}

// ---------------------------------------------------------------------------
// K5: gen = sigmoid(ctx.pg2 + x0.pg1 + h.pg3)
// ---------------------------------------------------------------------------
__global__ void k_gen(const float* __restrict__ x, const float* __restrict__ pg1,
                      const float* __restrict__ pg2, const float* __restrict__ pg3) {
    int b = blockIdx.x;
    __shared__ float red[32];
    float acc = 0.f;
    for (int k = threadIdx.x; k < In; k += blockDim.x) acc = fmaf(x[b * In + k], pg1[k], acc);
    for (int k = threadIdx.x; k < An; k += blockDim.x) acc = fmaf(g_ctx[b * An + k], pg2[k], acc);
    for (int k = threadIdx.x; k < Hn; k += blockDim.x) acc = fmaf(g_h[b * Hn + k], pg3[k], acc);
    acc = block_sum(acc, red);
    if (threadIdx.x == 0) g_gen[b] = sigmoidf(acc);
}

// ---------------------------------------------------------------------------
// K6: fc2 GEMM (256 x 50000 x 1024) with tf32 mma.sync; epilogue writes
//     exp(logit + bias) into g_exp (softmax done without max-subtraction:
//     logits are O(1), mathematically identical result).
// ---------------------------------------------------------------------------
#define BM 128
#define BN 128
#define BK 32
#define LDAS (BK + 4)   // 36 floats: conflict-free frag loads

__device__ __forceinline__ unsigned f2tf32(float f) {
    unsigned u;
    asm("cvt.rna.tf32.f32 %0, %1;" : "=r"(u) : "f"(f));
    return u;
}

__device__ __forceinline__ void mma_tf32(float c[4], const unsigned a[4], const unsigned b[2]) {
    asm volatile(
        "mma.sync.aligned.m16n8k8.row.col.f32.tf32.tf32.f32 "
        "{%0,%1,%2,%3}, {%4,%5,%6,%7}, {%8,%9}, {%0,%1,%2,%3};"
        : "+f"(c[0]), "+f"(c[1]), "+f"(c[2]), "+f"(c[3])
        : "r"(a[0]), "r"(a[1]), "r"(a[2]), "r"(a[3]), "r"(b[0]), "r"(b[1]));
}

__global__ __launch_bounds__(256, 1) void k_fc2(const float* __restrict__ fc2_w,
                                                const float* __restrict__ fc2_b) {
    __shared__ float As[BM][LDAS];
    __shared__ float Bs[BN][LDAS];
    int tid = threadIdx.x;
    int bm = blockIdx.y;            // 0..1
    int bn = blockIdx.x;            // 0..390
    int warp = tid >> 5, lane = tid & 31;
    int wm = warp >> 2;             // 0..1 -> row offset wm*64
    int wn = warp & 3;              // 0..3 -> col offset wn*32
    int nBase = bn * BN;

    float c[4][4][4];
    #pragma unroll
    for (int i = 0; i < 4; i++)
        #pragma unroll
        for (int j = 0; j < 4; j++)
            #pragma unroll
            for (int k = 0; k < 4; k++) c[i][j][k] = 0.f;

    for (int kt = 0; kt < H2; kt += BK) {
        // load A(128x32) and B(128x32) tiles, tf32-rounded
        #pragma unroll
        for (int p = 0; p < 4; p++) {
            int row = (tid >> 3) + p * 32;
            int c4 = (tid & 7) * 4;
            float4 va = *(const float4*)(g_fc1 + (size_t)(bm * BM + row) * H2 + kt + c4);
            As[row][c4 + 0] = __uint_as_float(f2tf32(va.x));
            As[row][c4 + 1] = __uint_as_float(f2tf32(va.y));
            As[row][c4 + 2] = __uint_as_float(f2tf32(va.z));
            As[row][c4 + 3] = __uint_as_float(f2tf32(va.w));
            int vrow = nBase + row;
            float4 vb = make_float4(0.f, 0.f, 0.f, 0.f);
            if (vrow < Vn)
                vb = *(const float4*)(fc2_w + (size_t)vrow * H2 + kt + c4);
            Bs[row][c4 + 0] = __uint_as_float(f2tf32(vb.x));
            Bs[row][c4 + 1] = __uint_as_float(f2tf32(vb.y));
            Bs[row][c4 + 2] = __uint_as_float(f2tf32(vb.z));
            Bs[row][c4 + 3] = __uint_as_float(f2tf32(vb.w));
        }
        __syncthreads();

        #pragma unroll
        for (int ks = 0; ks < BK; ks += 8) {
            unsigned afr[4][4], bfr[4][2];
            int k0 = ks + (lane & 3);
            #pragma unroll
            for (int mt = 0; mt < 4; mt++) {
                int r0 = wm * 64 + mt * 16 + (lane >> 2);
                afr[mt][0] = __float_as_uint(As[r0][k0]);
                afr[mt][1] = __float_as_uint(As[r0 + 8][k0]);
                afr[mt][2] = __float_as_uint(As[r0][k0 + 4]);
                afr[mt][3] = __float_as_uint(As[r0 + 8][k0 + 4]);
            }
            #pragma unroll
            for (int nt = 0; nt < 4; nt++) {
                int n0 = wn * 32 + nt * 8 + (lane >> 2);
                bfr[nt][0] = __float_as_uint(Bs[n0][k0]);
                bfr[nt][1] = __float_as_uint(Bs[n0][k0 + 4]);
            }
            #pragma unroll
            for (int mt = 0; mt < 4; mt++)
                #pragma unroll
                for (int nt = 0; nt < 4; nt++)
                    mma_tf32(c[mt][nt], afr[mt], bfr[nt]);
        }
        __syncthreads();
    }

    // epilogue: exp(logit + bias) -> g_exp
    #pragma unroll
    for (int mt = 0; mt < 4; mt++) {
        int r = bm * BM + wm * 64 + mt * 16 + (lane >> 2);
        #pragma unroll
        for (int nt = 0; nt < 4; nt++) {
            int col = nBase + wn * 32 + nt * 8 + 2 * (lane & 3);
            if (col < Vn) {
                g_exp[(size_t)r * Vn + col]       = expf(c[mt][nt][0] + fc2_b[col]);
                g_exp[(size_t)(r + 8) * Vn + col] = expf(c[mt][nt][2] + fc2_b[col]);
            }
            if (col + 1 < Vn) {
                g_exp[(size_t)r * Vn + col + 1]       = expf(c[mt][nt][1] + fc2_b[col + 1]);
                g_exp[(size_t)(r + 8) * Vn + col + 1] = expf(c[mt][nt][3] + fc2_b[col + 1]);
            }
        }
    }
}

// ---------------------------------------------------------------------------
// K7: row sums of g_exp
// ---------------------------------------------------------------------------
__global__ void k_sum() {
    int b = blockIdx.x;
    __shared__ float red[32];
    const float4* p = (const float4*)(g_exp + (size_t)b * Vn);
    float s = 0.f;
    for (int i = threadIdx.x; i < Vn / 4; i += blockDim.x) {
        float4 q = p[i];
        s += q.x + q.y + q.z + q.w;
    }
    s = block_sum(s, red);
    if (threadIdx.x == 0) g_sum[b] = s;
}

// ---------------------------------------------------------------------------
// K8: out[b, v] = v < V ? gen*exp/sum : 0   (covers all 50050 cols)
// ---------------------------------------------------------------------------
__global__ void k_final(float* __restrict__ out) {
    int b = blockIdx.y;
    int v = blockIdx.x * blockDim.x + threadIdx.x;
    if (v >= Pn) return;
    float scale = g_gen[b] / g_sum[b];
    float r = 0.f;
    if (v < Vn) r = scale * g_exp[(size_t)b * Vn + v];
    out[(size_t)b * Pn + v] = r;
}

// ---------------------------------------------------------------------------
// K9: scatter-add pointer probabilities
// ---------------------------------------------------------------------------
__global__ void k_scatter(float* __restrict__ out, const int* __restrict__ ids) {
    int b = blockIdx.x;
    int a = threadIdx.x;
    if (a < An) {
        float w = (1.0f - g_gen[b]) * g_att[b * An + a];
        int id = ids[b * An + a];
        atomicAdd(&out[(size_t)b * Pn + id], w);
    }
}

// ---------------------------------------------------------------------------
extern "C" void kernel_launch(void* const* d_in, const int* in_sizes, int n_in,
                              void* d_out, int out_size) {
    const float* x         = (const float*)d_in[0];
    const float* enc_out   = (const float*)d_in[2];
    const float* enc_state = (const float*)d_in[4];
    const int*   ids       = (const int*)d_in[6];
    const float* W_ih      = (const float*)d_in[7];
    const float* b_ih      = (const float*)d_in[9];
    const float* b_hh      = (const float*)d_in[10];
    const float* Wh_w      = (const float*)d_in[11];
    const float* Wh_b      = (const float*)d_in[12];
    const float* Ws_w      = (const float*)d_in[13];
    const float* Ws_b      = (const float*)d_in[14];
    const float* vvec      = (const float*)d_in[15];
    const float* fc1_w     = (const float*)d_in[16];
    const float* fc1_b     = (const float*)d_in[17];
    const float* fc2_w     = (const float*)d_in[18];
    const float* fc2_b     = (const float*)d_in[19];
    const float* pg1       = (const float*)d_in[20];
    const float* pg2       = (const float*)d_in[21];
    const float* pg3       = (const float*)d_in[22];
    float* out = (float*)d_out;

    k_lstm<<<Bn, 256>>>(x, W_ih, b_ih, b_hh);
    k_attn<<<Bn, 256>>>(enc_state, Wh_w, Wh_b, Ws_w, Ws_b, vvec);
    k_ctx<<<dim3(4, Bn), 416>>>(enc_out);
    k_ctxred<<<Bn, 416>>>();
    k_fc1<<<Bn, 256>>>(fc1_w, fc1_b);
    k_gen<<<Bn, 256>>>(x, pg1, pg2, pg3);
    k_fc2<<<dim3((Vn + BN - 1) / BN, Bn / BM), 256>>>(fc2_w, fc2_b);
    k_sum<<<Bn, 1024>>>();
    k_final<<<dim3((Pn + 255) / 256, Bn), 256>>>(out);
    k_scatter<<<Bn, 416>>>(out, ids);
}

// round 6
// speedup vs baseline: 1.1662x; 1.1662x over previous
#include <cuda_runtime.h>
#include <math.h>

// Problem constants
#define Bn   256
#define In   256
#define Hn   512
#define An   400
#define Vn   50000
#define OOVn 50
#define Pn   (Vn + OOVn)      // 50050
#define H2   (2 * Hn)          // 1024
#define DIN  (An + Hn)         // 912
#define NBN  391               // fc2 n-blocks (391*128 = 50048)

// Scratch (static device globals: allocation-free rule)
__device__ float g_h[Bn * Hn];
__device__ float g_att[Bn * An];
__device__ float g_ctxp[4 * Bn * An];
__device__ float g_ctx[Bn * An];
__device__ float g_fc1[Bn * H2];
__device__ float g_gen[Bn];
__device__ float g_sum[Bn];
__device__ float g_exp[(size_t)Bn * Vn];   // 51.2 MB

__device__ __forceinline__ float sigmoidf(float x) { return 1.0f / (1.0f + expf(-x)); }

__device__ __forceinline__ float warp_sum(float v) {
    #pragma unroll
    for (int o = 16; o; o >>= 1) v += __shfl_xor_sync(0xFFFFFFFFu, v, o);
    return v;
}

__device__ __forceinline__ float block_sum(float v, float* red) {
    int lane = threadIdx.x & 31, warp = threadIdx.x >> 5;
    v = warp_sum(v);
    if (lane == 0) red[warp] = v;
    __syncthreads();
    int nw = (blockDim.x + 31) >> 5;
    float r = (threadIdx.x < nw) ? red[threadIdx.x] : 0.0f;
    if (warp == 0) r = warp_sum(r);
    if (threadIdx.x == 0) red[0] = r;
    __syncthreads();
    return red[0];
}

__device__ __forceinline__ float block_max(float v, float* red) {
    int lane = threadIdx.x & 31, warp = threadIdx.x >> 5;
    #pragma unroll
    for (int o = 16; o; o >>= 1) v = fmaxf(v, __shfl_xor_sync(0xFFFFFFFFu, v, o));
    if (lane == 0) red[warp] = v;
    __syncthreads();
    int nw = (blockDim.x + 31) >> 5;
    float r = (threadIdx.x < nw) ? red[threadIdx.x] : -INFINITY;
    if (warp == 0) {
        #pragma unroll
        for (int o = 16; o; o >>= 1) r = fmaxf(r, __shfl_xor_sync(0xFFFFFFFFu, r, o));
    }
    if (threadIdx.x == 0) red[0] = r;
    __syncthreads();
    return red[0];
}

// ---------------------------------------------------------------------------
// K1: degenerate LSTM cell (as R1, proven)
// ---------------------------------------------------------------------------
__global__ void k_lstm(const float* __restrict__ x, const float* __restrict__ W_ih,
                       const float* __restrict__ b_ih, const float* __restrict__ b_hh) {
    int b = blockIdx.x;
    __shared__ float sx[In];
    for (int i = threadIdx.x; i < In; i += blockDim.x) sx[i] = x[b * In + i];
    __syncthreads();
    int warp = threadIdx.x >> 5, lane = threadIdx.x & 31;
    for (int j = warp; j < Hn; j += (blockDim.x >> 5)) {
        const float* wi = W_ih + (size_t)j * In;
        const float* wg = W_ih + (size_t)(2 * Hn + j) * In;
        const float* wo = W_ih + (size_t)(3 * Hn + j) * In;
        float ai = 0.f, ag = 0.f, ao = 0.f;
        for (int k = lane; k < In; k += 32) {
            float xv = sx[k];
            ai = fmaf(xv, wi[k], ai);
            ag = fmaf(xv, wg[k], ag);
            ao = fmaf(xv, wo[k], ao);
        }
        ai = warp_sum(ai); ag = warp_sum(ag); ao = warp_sum(ao);
        if (lane == 0) {
            ai += b_ih[j] + b_hh[j];
            ag += b_ih[2 * Hn + j] + b_hh[2 * Hn + j];
            ao += b_ih[3 * Hn + j] + b_hh[3 * Hn + j];
            float c = sigmoidf(ai) * tanhf(ag);
            g_h[b * Hn + j] = sigmoidf(ao) * tanhf(c);
        }
    }
}

// ---------------------------------------------------------------------------
// K2: attention (as R1, proven)
// ---------------------------------------------------------------------------
__global__ void k_attn(const float* __restrict__ enc_state,
                       const float* __restrict__ Wh_w, const float* __restrict__ Wh_b,
                       const float* __restrict__ Ws_w, const float* __restrict__ Ws_b,
                       const float* __restrict__ vvec) {
    int b = blockIdx.x;
    __shared__ float ss[Hn], sh[Hn], se[An], red[32];
    for (int i = threadIdx.x; i < Hn; i += blockDim.x) {
        ss[i] = enc_state[b * Hn + i];
        sh[i] = g_h[b * Hn + i];
    }
    __syncthreads();
    int warp = threadIdx.x >> 5, lane = threadIdx.x & 31;
    for (int a = warp; a < An; a += (blockDim.x >> 5)) {
        const float* w1 = Wh_w + (size_t)a * Hn;
        const float* w2 = Ws_w + (size_t)a * Hn;
        float acc = 0.f;
        for (int k = lane; k < Hn; k += 32)
            acc = fmaf(ss[k], w1[k], fmaf(sh[k], w2[k], acc));
        acc = warp_sum(acc);
        if (lane == 0) se[a] = tanhf(acc + Wh_b[a] + Ws_b[a]);
    }
    __syncthreads();
    float m = -INFINITY;
    for (int i = threadIdx.x; i < An; i += blockDim.x) m = fmaxf(m, se[i]);
    m = block_max(m, red);
    float s = 0.f;
    for (int i = threadIdx.x; i < An; i += blockDim.x) s += expf(se[i] - m);
    s = block_sum(s, red);
    float inv = 1.0f / s;
    for (int i = threadIdx.x; i < An; i += blockDim.x)
        g_att[b * An + i] = vvec[i] * expf(se[i] - m) * inv;
}

// ---------------------------------------------------------------------------
// K3: context partials (as R1, proven scalar version)
// ---------------------------------------------------------------------------
__global__ void k_ctx(const float* __restrict__ enc_out) {
    int slice = blockIdx.x;     // 0..3
    int b = blockIdx.y;         // 0..255
    int a0 = slice * 100;
    __shared__ float sa[100];
    if (threadIdx.x < 100) sa[threadIdx.x] = g_att[b * An + a0 + threadIdx.x];
    __syncthreads();
    int e = threadIdx.x;
    if (e < An) {
        const float* base = enc_out + ((size_t)b * An + a0) * An + e;
        float acc = 0.f;
        #pragma unroll 5
        for (int i = 0; i < 100; i++) acc = fmaf(sa[i], base[(size_t)i * An], acc);
        g_ctxp[((size_t)slice * Bn + b) * An + e] = acc;
    }
}

__global__ void k_ctxred() {
    int b = blockIdx.x;
    int e = threadIdx.x;
    if (e < An) {
        float s = g_ctxp[((size_t)0 * Bn + b) * An + e]
                + g_ctxp[((size_t)1 * Bn + b) * An + e]
                + g_ctxp[((size_t)2 * Bn + b) * An + e]
                + g_ctxp[((size_t)3 * Bn + b) * An + e];
        g_ctx[b * An + e] = s;
    }
}

// ---------------------------------------------------------------------------
// K4: fc1 fp32 (as R1, proven)
// ---------------------------------------------------------------------------
__global__ void k_fc1(const float* __restrict__ fc1_w, const float* __restrict__ fc1_b) {
    int b = blockIdx.x;
    __shared__ float sd[DIN];
    for (int i = threadIdx.x; i < An; i += blockDim.x) sd[i] = g_ctx[b * An + i];
    for (int i = threadIdx.x; i < Hn; i += blockDim.x) sd[An + i] = g_h[b * Hn + i];
    __syncthreads();
    int warp = threadIdx.x >> 5, lane = threadIdx.x & 31;
    for (int j = warp; j < H2; j += (blockDim.x >> 5)) {
        const float* w = fc1_w + (size_t)j * DIN;
        float acc = 0.f;
        for (int k = lane; k < DIN; k += 32) acc = fmaf(sd[k], w[k], acc);
        acc = warp_sum(acc);
        if (lane == 0) g_fc1[b * H2 + j] = acc + fc1_b[j];
    }
}

// ---------------------------------------------------------------------------
// K5: gen gate (as R1, proven)
// ---------------------------------------------------------------------------
__global__ void k_gen(const float* __restrict__ x, const float* __restrict__ pg1,
                      const float* __restrict__ pg2, const float* __restrict__ pg3) {
    int b = blockIdx.x;
    __shared__ float red[32];
    float acc = 0.f;
    for (int k = threadIdx.x; k < In; k += blockDim.x) acc = fmaf(x[b * In + k], pg1[k], acc);
    for (int k = threadIdx.x; k < An; k += blockDim.x) acc = fmaf(g_ctx[b * An + k], pg2[k], acc);
    for (int k = threadIdx.x; k < Hn; k += blockDim.x) acc = fmaf(g_h[b * Hn + k], pg3[k], acc);
    acc = block_sum(acc, red);
    if (threadIdx.x == 0) g_gen[b] = sigmoidf(acc);
}

// ---------------------------------------------------------------------------
// K6: fc2 GEMM (256 x 50000 x 1024) tf32 mma.sync, cp.async double-buffered
// BK=16, cvt.rna on registers (same numerics as R1's store-time convert).
// Epilogue: exp(logit + bias) -> g_exp.
// ---------------------------------------------------------------------------
#define CP_ASYNC(dst, src)        asm volatile("cp.async.cg.shared.global [%0], [%1], 16;" :: "r"(dst), "l"(src))
#define CP_ASYNC_Z(dst, src, sz)  asm volatile("cp.async.cg.shared.global [%0], [%1], 16, %2;" :: "r"(dst), "l"(src), "r"(sz))
#define CP_COMMIT()               asm volatile("cp.async.commit_group;")
#define CP_WAIT(n)                asm volatile("cp.async.wait_group %0;" :: "n"(n))

__device__ __forceinline__ unsigned f2tf32(float f) {
    unsigned u;
    asm("cvt.rna.tf32.f32 %0, %1;" : "=r"(u) : "f"(f));
    return u;
}

__device__ __forceinline__ void mma_tf32(float c[4], const unsigned a[4], const unsigned b[2]) {
    asm volatile(
        "mma.sync.aligned.m16n8k8.row.col.f32.tf32.tf32.f32 "
        "{%0,%1,%2,%3}, {%4,%5,%6,%7}, {%8,%9}, {%0,%1,%2,%3};"
        : "+f"(c[0]), "+f"(c[1]), "+f"(c[2]), "+f"(c[3])
        : "r"(a[0]), "r"(a[1]), "r"(a[2]), "r"(a[3]), "r"(b[0]), "r"(b[1]));
}

#define LDP 20   // float pitch per smem row (16 data + 4 pad)
#define KT2 (H2 / 16)   // 64 k-tiles

__global__ __launch_bounds__(256, 1) void k_fc2(const float* __restrict__ fc2_w,
                                                const float* __restrict__ fc2_b) {
    __shared__ float As[2][128][LDP];
    __shared__ float Bs[2][128][LDP];

    int tid = threadIdx.x;
    int bm = blockIdx.y;            // 0..1
    int bn = blockIdx.x;            // 0..390
    int warp = tid >> 5, lane = tid & 31;
    int wm = warp >> 2;             // 0..1 -> row offset wm*64
    int wn = warp & 3;              // 0..3 -> col offset wn*32
    int nBase = bn * 128;

    float c[4][4][4];
    #pragma unroll
    for (int i = 0; i < 4; i++)
        #pragma unroll
        for (int j = 0; j < 4; j++)
            #pragma unroll
            for (int k = 0; k < 4; k++) c[i][j][k] = 0.f;

    // copy map: 128 rows x 16 floats = 512 chunks of 16B; 2 per thread
    int crow0 = tid >> 2;                 // rows 0..63
    int coff0 = (tid & 3);
    int crow1 = (tid + 256) >> 2;         // rows 64..127
    int coff1 = ((tid + 256) & 3);
    int bok0 = (nBase + crow0 < Vn) ? 16 : 0;
    int bok1 = (nBase + crow1 < Vn) ? 16 : 0;

    const float* A = g_fc1;

    auto issue = [&](int kt, int s) {
        const float* a0 = A + (size_t)(bm * 128 + crow0) * H2 + kt * 16 + coff0 * 4;
        const float* a1 = A + (size_t)(bm * 128 + crow1) * H2 + kt * 16 + coff1 * 4;
        const float* b0 = fc2_w + (size_t)(nBase + crow0) * H2 + kt * 16 + coff0 * 4;
        const float* b1 = fc2_w + (size_t)(nBase + crow1) * H2 + kt * 16 + coff1 * 4;
        unsigned da0 = (unsigned)__cvta_generic_to_shared(&As[s][crow0][coff0 * 4]);
        unsigned da1 = (unsigned)__cvta_generic_to_shared(&As[s][crow1][coff1 * 4]);
        unsigned db0 = (unsigned)__cvta_generic_to_shared(&Bs[s][crow0][coff0 * 4]);
        unsigned db1 = (unsigned)__cvta_generic_to_shared(&Bs[s][crow1][coff1 * 4]);
        CP_ASYNC(da0, a0); CP_ASYNC(da1, a1);
        CP_ASYNC_Z(db0, b0, bok0); CP_ASYNC_Z(db1, b1, bok1);
        CP_COMMIT();
    };

    issue(0, 0);

    for (int kt = 0; kt < KT2; kt++) {
        int s = kt & 1;
        if (kt + 1 < KT2) {
            issue(kt + 1, s ^ 1);
            CP_WAIT(1);
        } else {
            CP_WAIT(0);
        }
        __syncthreads();

        #pragma unroll
        for (int ks = 0; ks < 2; ks++) {
            unsigned afr[4][4], bfr[4][2];
            int k0 = ks * 8 + (lane & 3);
            #pragma unroll
            for (int mt = 0; mt < 4; mt++) {
                int r0 = wm * 64 + mt * 16 + (lane >> 2);
                afr[mt][0] = f2tf32(As[s][r0][k0]);
                afr[mt][1] = f2tf32(As[s][r0 + 8][k0]);
                afr[mt][2] = f2tf32(As[s][r0][k0 + 4]);
                afr[mt][3] = f2tf32(As[s][r0 + 8][k0 + 4]);
            }
            #pragma unroll
            for (int nt = 0; nt < 4; nt++) {
                int n0 = wn * 32 + nt * 8 + (lane >> 2);
                bfr[nt][0] = f2tf32(Bs[s][n0][k0]);
                bfr[nt][1] = f2tf32(Bs[s][n0][k0 + 4]);
            }
            #pragma unroll
            for (int mt = 0; mt < 4; mt++)
                #pragma unroll
                for (int nt = 0; nt < 4; nt++)
                    mma_tf32(c[mt][nt], afr[mt], bfr[nt]);
        }
        __syncthreads();
    }

    // epilogue: exp(logit + bias) -> g_exp  (as R1, proven)
    #pragma unroll
    for (int mt = 0; mt < 4; mt++) {
        int r = bm * 128 + wm * 64 + mt * 16 + (lane >> 2);
        #pragma unroll
        for (int nt = 0; nt < 4; nt++) {
            int col = nBase + wn * 32 + nt * 8 + 2 * (lane & 3);
            if (col < Vn) {
                g_exp[(size_t)r * Vn + col]       = expf(c[mt][nt][0] + fc2_b[col]);
                g_exp[(size_t)(r + 8) * Vn + col] = expf(c[mt][nt][2] + fc2_b[col]);
            }
            if (col + 1 < Vn) {
                g_exp[(size_t)r * Vn + col + 1]       = expf(c[mt][nt][1] + fc2_b[col + 1]);
                g_exp[(size_t)(r + 8) * Vn + col + 1] = expf(c[mt][nt][3] + fc2_b[col + 1]);
            }
        }
    }
}

// ---------------------------------------------------------------------------
// K7: row sums of g_exp (as R1, proven)
// ---------------------------------------------------------------------------
__global__ void k_sum() {
    int b = blockIdx.x;
    __shared__ float red[32];
    const float4* p = (const float4*)(g_exp + (size_t)b * Vn);
    float s = 0.f;
    for (int i = threadIdx.x; i < Vn / 4; i += blockDim.x) {
        float4 q = p[i];
        s += q.x + q.y + q.z + q.w;
    }
    s = block_sum(s, red);
    if (threadIdx.x == 0) g_sum[b] = s;
}

// ---------------------------------------------------------------------------
// K8: finalize (as R1, proven)
// ---------------------------------------------------------------------------
__global__ void k_final(float* __restrict__ out) {
    int b = blockIdx.y;
    int v = blockIdx.x * blockDim.x + threadIdx.x;
    if (v >= Pn) return;
    float scale = g_gen[b] / g_sum[b];
    float r = 0.f;
    if (v < Vn) r = scale * g_exp[(size_t)b * Vn + v];
    out[(size_t)b * Pn + v] = r;
}

// ---------------------------------------------------------------------------
// K9: scatter-add (as R1, proven)
// ---------------------------------------------------------------------------
__global__ void k_scatter(float* __restrict__ out, const int* __restrict__ ids) {
    int b = blockIdx.x;
    int a = threadIdx.x;
    if (a < An) {
        float w = (1.0f - g_gen[b]) * g_att[b * An + a];
        int id = ids[b * An + a];
        atomicAdd(&out[(size_t)b * Pn + id], w);
    }
}

// ---------------------------------------------------------------------------
extern "C" void kernel_launch(void* const* d_in, const int* in_sizes, int n_in,
                              void* d_out, int out_size) {
    const float* x         = (const float*)d_in[0];
    const float* enc_out   = (const float*)d_in[2];
    const float* enc_state = (const float*)d_in[4];
    const int*   ids       = (const int*)d_in[6];
    const float* W_ih      = (const float*)d_in[7];
    const float* b_ih      = (const float*)d_in[9];
    const float* b_hh      = (const float*)d_in[10];
    const float* Wh_w      = (const float*)d_in[11];
    const float* Wh_b      = (const float*)d_in[12];
    const float* Ws_w      = (const float*)d_in[13];
    const float* Ws_b      = (const float*)d_in[14];
    const float* vvec      = (const float*)d_in[15];
    const float* fc1_w     = (const float*)d_in[16];
    const float* fc1_b     = (const float*)d_in[17];
    const float* fc2_w     = (const float*)d_in[18];
    const float* fc2_b     = (const float*)d_in[19];
    const float* pg1       = (const float*)d_in[20];
    const float* pg2       = (const float*)d_in[21];
    const float* pg3       = (const float*)d_in[22];
    float* out = (float*)d_out;

    k_lstm<<<Bn, 256>>>(x, W_ih, b_ih, b_hh);
    k_attn<<<Bn, 256>>>(enc_state, Wh_w, Wh_b, Ws_w, Ws_b, vvec);
    k_ctx<<<dim3(4, Bn), 416>>>(enc_out);
    k_ctxred<<<Bn, 416>>>();
    k_fc1<<<Bn, 256>>>(fc1_w, fc1_b);
    k_gen<<<Bn, 256>>>(x, pg1, pg2, pg3);
    k_fc2<<<dim3(NBN, Bn / 128), 256>>>(fc2_w, fc2_b);
    k_sum<<<Bn, 1024>>>();
    k_final<<<dim3((Pn + 255) / 256, Bn), 256>>>(out);
    k_scatter<<<Bn, 416>>>(out, ids);
}

// round 7
// speedup vs baseline: 1.3664x; 1.1716x over previous
#include <cuda_runtime.h>
#include <math.h>

// Problem constants
#define Bn   256
#define In   256
#define Hn   512
#define An   400
#define Vn   50000
#define OOVn 50
#define Pn   (Vn + OOVn)      // 50050
#define H2   (2 * Hn)          // 1024
#define DIN  (An + Hn)         // 912 = 57*16
#define NBN  391               // fc2 n-blocks (391*128 = 50048)

// Scratch (static device globals: allocation-free rule)
__device__ float g_h[Bn * Hn];
__device__ float g_att[Bn * An];
__device__ float g_ctxp[4 * Bn * An];
__device__ float g_ctx[Bn * An];
__device__ float g_din[Bn * DIN];
__device__ float g_fc1[Bn * H2];
__device__ float g_gen[Bn];
__device__ float g_sum[Bn];
__device__ float g_exp[(size_t)Bn * Vn];   // 51.2 MB

__device__ __forceinline__ float sigmoidf(float x) { return 1.0f / (1.0f + expf(-x)); }

__device__ __forceinline__ float warp_sum(float v) {
    #pragma unroll
    for (int o = 16; o; o >>= 1) v += __shfl_xor_sync(0xFFFFFFFFu, v, o);
    return v;
}

__device__ __forceinline__ float block_sum(float v, float* red) {
    int lane = threadIdx.x & 31, warp = threadIdx.x >> 5;
    v = warp_sum(v);
    if (lane == 0) red[warp] = v;
    __syncthreads();
    int nw = (blockDim.x + 31) >> 5;
    float r = (threadIdx.x < nw) ? red[threadIdx.x] : 0.0f;
    if (warp == 0) r = warp_sum(r);
    if (threadIdx.x == 0) red[0] = r;
    __syncthreads();
    return red[0];
}

__device__ __forceinline__ float block_max(float v, float* red) {
    int lane = threadIdx.x & 31, warp = threadIdx.x >> 5;
    #pragma unroll
    for (int o = 16; o; o >>= 1) v = fmaxf(v, __shfl_xor_sync(0xFFFFFFFFu, v, o));
    if (lane == 0) red[warp] = v;
    __syncthreads();
    int nw = (blockDim.x + 31) >> 5;
    float r = (threadIdx.x < nw) ? red[threadIdx.x] : -INFINITY;
    if (warp == 0) {
        #pragma unroll
        for (int o = 16; o; o >>= 1) r = fmaxf(r, __shfl_xor_sync(0xFFFFFFFFu, r, o));
    }
    if (threadIdx.x == 0) red[0] = r;
    __syncthreads();
    return red[0];
}

// ---------------------------------------------------------------------------
// K1: degenerate LSTM cell (proven)
// ---------------------------------------------------------------------------
__global__ void k_lstm(const float* __restrict__ x, const float* __restrict__ W_ih,
                       const float* __restrict__ b_ih, const float* __restrict__ b_hh) {
    int b = blockIdx.x;
    __shared__ float sx[In];
    for (int i = threadIdx.x; i < In; i += blockDim.x) sx[i] = x[b * In + i];
    __syncthreads();
    int warp = threadIdx.x >> 5, lane = threadIdx.x & 31;
    for (int j = warp; j < Hn; j += (blockDim.x >> 5)) {
        const float* wi = W_ih + (size_t)j * In;
        const float* wg = W_ih + (size_t)(2 * Hn + j) * In;
        const float* wo = W_ih + (size_t)(3 * Hn + j) * In;
        float ai = 0.f, ag = 0.f, ao = 0.f;
        for (int k = lane; k < In; k += 32) {
            float xv = sx[k];
            ai = fmaf(xv, wi[k], ai);
            ag = fmaf(xv, wg[k], ag);
            ao = fmaf(xv, wo[k], ao);
        }
        ai = warp_sum(ai); ag = warp_sum(ag); ao = warp_sum(ao);
        if (lane == 0) {
            ai += b_ih[j] + b_hh[j];
            ag += b_ih[2 * Hn + j] + b_hh[2 * Hn + j];
            ao += b_ih[3 * Hn + j] + b_hh[3 * Hn + j];
            float c = sigmoidf(ai) * tanhf(ag);
            g_h[b * Hn + j] = sigmoidf(ao) * tanhf(c);
        }
    }
}

// ---------------------------------------------------------------------------
// K2: attention (proven)
// ---------------------------------------------------------------------------
__global__ void k_attn(const float* __restrict__ enc_state,
                       const float* __restrict__ Wh_w, const float* __restrict__ Wh_b,
                       const float* __restrict__ Ws_w, const float* __restrict__ Ws_b,
                       const float* __restrict__ vvec) {
    int b = blockIdx.x;
    __shared__ float ss[Hn], sh[Hn], se[An], red[32];
    for (int i = threadIdx.x; i < Hn; i += blockDim.x) {
        ss[i] = enc_state[b * Hn + i];
        sh[i] = g_h[b * Hn + i];
    }
    __syncthreads();
    int warp = threadIdx.x >> 5, lane = threadIdx.x & 31;
    for (int a = warp; a < An; a += (blockDim.x >> 5)) {
        const float* w1 = Wh_w + (size_t)a * Hn;
        const float* w2 = Ws_w + (size_t)a * Hn;
        float acc = 0.f;
        for (int k = lane; k < Hn; k += 32)
            acc = fmaf(ss[k], w1[k], fmaf(sh[k], w2[k], acc));
        acc = warp_sum(acc);
        if (lane == 0) se[a] = tanhf(acc + Wh_b[a] + Ws_b[a]);
    }
    __syncthreads();
    float m = -INFINITY;
    for (int i = threadIdx.x; i < An; i += blockDim.x) m = fmaxf(m, se[i]);
    m = block_max(m, red);
    float s = 0.f;
    for (int i = threadIdx.x; i < An; i += blockDim.x) s += expf(se[i] - m);
    s = block_sum(s, red);
    float inv = 1.0f / s;
    for (int i = threadIdx.x; i < An; i += blockDim.x)
        g_att[b * An + i] = vvec[i] * expf(se[i] - m) * inv;
}

// ---------------------------------------------------------------------------
// K3: context partials (proven scalar version)
// ---------------------------------------------------------------------------
__global__ void k_ctx(const float* __restrict__ enc_out) {
    int slice = blockIdx.x;     // 0..3
    int b = blockIdx.y;         // 0..255
    int a0 = slice * 100;
    __shared__ float sa[100];
    if (threadIdx.x < 100) sa[threadIdx.x] = g_att[b * An + a0 + threadIdx.x];
    __syncthreads();
    int e = threadIdx.x;
    if (e < An) {
        const float* base = enc_out + ((size_t)b * An + a0) * An + e;
        float acc = 0.f;
        #pragma unroll 5
        for (int i = 0; i < 100; i++) acc = fmaf(sa[i], base[(size_t)i * An], acc);
        g_ctxp[((size_t)slice * Bn + b) * An + e] = acc;
    }
}

__global__ void k_ctxred() {
    int b = blockIdx.x;
    int e = threadIdx.x;
    if (e < An) {
        float s = g_ctxp[((size_t)0 * Bn + b) * An + e]
                + g_ctxp[((size_t)1 * Bn + b) * An + e]
                + g_ctxp[((size_t)2 * Bn + b) * An + e]
                + g_ctxp[((size_t)3 * Bn + b) * An + e];
        g_ctx[b * An + e] = s;
    }
}

// ---------------------------------------------------------------------------
// K5: gen gate (proven) + dec_in assembly
// ---------------------------------------------------------------------------
__global__ void k_gen(const float* __restrict__ x, const float* __restrict__ pg1,
                      const float* __restrict__ pg2, const float* __restrict__ pg3) {
    int b = blockIdx.x;
    __shared__ float red[32];
    float acc = 0.f;
    for (int k = threadIdx.x; k < In; k += blockDim.x) acc = fmaf(x[b * In + k], pg1[k], acc);
    for (int k = threadIdx.x; k < An; k += blockDim.x) acc = fmaf(g_ctx[b * An + k], pg2[k], acc);
    for (int k = threadIdx.x; k < Hn; k += blockDim.x) acc = fmaf(g_h[b * Hn + k], pg3[k], acc);
    acc = block_sum(acc, red);
    if (threadIdx.x == 0) g_gen[b] = sigmoidf(acc);
}

__global__ void k_din() {
    int b = blockIdx.x;
    for (int i = threadIdx.x; i < DIN; i += blockDim.x) {
        float v = (i < An) ? g_ctx[b * An + i] : g_h[b * Hn + (i - An)];
        g_din[b * DIN + i] = v;
    }
}

// ---------------------------------------------------------------------------
// tf32 MMA machinery (raw fp32 bits fed to tf32 MMA: HW truncation, no CVT)
// ---------------------------------------------------------------------------
#define CP_ASYNC(dst, src)        asm volatile("cp.async.cg.shared.global [%0], [%1], 16;" :: "r"(dst), "l"(src))
#define CP_ASYNC_Z(dst, src, sz)  asm volatile("cp.async.cg.shared.global [%0], [%1], 16, %2;" :: "r"(dst), "l"(src), "r"(sz))
#define CP_COMMIT()               asm volatile("cp.async.commit_group;")
#define CP_WAIT(n)                asm volatile("cp.async.wait_group %0;" :: "n"(n))

__device__ __forceinline__ void mma_tf32(float c[4], const unsigned a[4], const unsigned b[2]) {
    asm volatile(
        "mma.sync.aligned.m16n8k8.row.col.f32.tf32.tf32.f32 "
        "{%0,%1,%2,%3}, {%4,%5,%6,%7}, {%8,%9}, {%0,%1,%2,%3};"
        : "+f"(c[0]), "+f"(c[1]), "+f"(c[2]), "+f"(c[3])
        : "r"(a[0]), "r"(a[1]), "r"(a[2]), "r"(a[3]), "r"(b[0]), "r"(b[1]));
}

#define LDP 20   // float pitch per smem row (16 data + 4 pad) — conflict-free frag loads
#define KT2 (H2 / 16)    // 64 k-tiles for fc2
#define KT1 (DIN / 16)   // 57 k-tiles for fc1

// ---------------------------------------------------------------------------
// K6: fc2 GEMM (256 x 50000 x 1024), cp.async double-buffered, raw tf32 feed.
// Epilogue: exp(logit + bias) -> g_exp (proven R1/R6 epilogue).
// ---------------------------------------------------------------------------
__global__ __launch_bounds__(256, 1) void k_fc2(const float* __restrict__ fc2_w,
                                                const float* __restrict__ fc2_b) {
    __shared__ float As[2][128][LDP];
    __shared__ float Bs[2][128][LDP];

    int tid = threadIdx.x;
    int bm = blockIdx.y;            // 0..1
    int bn = blockIdx.x;            // 0..390
    int warp = tid >> 5, lane = tid & 31;
    int wm = warp >> 2;             // 0..1 -> row offset wm*64
    int wn = warp & 3;              // 0..3 -> col offset wn*32
    int nBase = bn * 128;

    float c[4][4][4];
    #pragma unroll
    for (int i = 0; i < 4; i++)
        #pragma unroll
        for (int j = 0; j < 4; j++)
            #pragma unroll
            for (int k = 0; k < 4; k++) c[i][j][k] = 0.f;

    int crow0 = tid >> 2;                 // rows 0..63
    int coff0 = (tid & 3);
    int crow1 = (tid + 256) >> 2;         // rows 64..127
    int coff1 = ((tid + 256) & 3);
    int bok0 = (nBase + crow0 < Vn) ? 16 : 0;
    int bok1 = (nBase + crow1 < Vn) ? 16 : 0;

    const float* A = g_fc1;

    auto issue = [&](int kt, int s) {
        const float* a0 = A + (size_t)(bm * 128 + crow0) * H2 + kt * 16 + coff0 * 4;
        const float* a1 = A + (size_t)(bm * 128 + crow1) * H2 + kt * 16 + coff1 * 4;
        const float* b0 = fc2_w + (size_t)(nBase + crow0) * H2 + kt * 16 + coff0 * 4;
        const float* b1 = fc2_w + (size_t)(nBase + crow1) * H2 + kt * 16 + coff1 * 4;
        unsigned da0 = (unsigned)__cvta_generic_to_shared(&As[s][crow0][coff0 * 4]);
        unsigned da1 = (unsigned)__cvta_generic_to_shared(&As[s][crow1][coff1 * 4]);
        unsigned db0 = (unsigned)__cvta_generic_to_shared(&Bs[s][crow0][coff0 * 4]);
        unsigned db1 = (unsigned)__cvta_generic_to_shared(&Bs[s][crow1][coff1 * 4]);
        CP_ASYNC(da0, a0); CP_ASYNC(da1, a1);
        CP_ASYNC_Z(db0, b0, bok0); CP_ASYNC_Z(db1, b1, bok1);
        CP_COMMIT();
    };

    issue(0, 0);

    for (int kt = 0; kt < KT2; kt++) {
        int s = kt & 1;
        if (kt + 1 < KT2) {
            issue(kt + 1, s ^ 1);
            CP_WAIT(1);
        } else {
            CP_WAIT(0);
        }
        __syncthreads();

        #pragma unroll
        for (int ks = 0; ks < 2; ks++) {
            unsigned afr[4][4], bfr[4][2];
            int k0 = ks * 8 + (lane & 3);
            #pragma unroll
            for (int mt = 0; mt < 4; mt++) {
                int r0 = wm * 64 + mt * 16 + (lane >> 2);
                afr[mt][0] = __float_as_uint(As[s][r0][k0]);
                afr[mt][1] = __float_as_uint(As[s][r0 + 8][k0]);
                afr[mt][2] = __float_as_uint(As[s][r0][k0 + 4]);
                afr[mt][3] = __float_as_uint(As[s][r0 + 8][k0 + 4]);
            }
            #pragma unroll
            for (int nt = 0; nt < 4; nt++) {
                int n0 = wn * 32 + nt * 8 + (lane >> 2);
                bfr[nt][0] = __float_as_uint(Bs[s][n0][k0]);
                bfr[nt][1] = __float_as_uint(Bs[s][n0][k0 + 4]);
            }
            #pragma unroll
            for (int mt = 0; mt < 4; mt++)
                #pragma unroll
                for (int nt = 0; nt < 4; nt++)
                    mma_tf32(c[mt][nt], afr[mt], bfr[nt]);
        }
        __syncthreads();
    }

    // epilogue: exp(logit + bias) -> g_exp
    #pragma unroll
    for (int mt = 0; mt < 4; mt++) {
        int r = bm * 128 + wm * 64 + mt * 16 + (lane >> 2);
        #pragma unroll
        for (int nt = 0; nt < 4; nt++) {
            int col = nBase + wn * 32 + nt * 8 + 2 * (lane & 3);
            if (col < Vn) {
                g_exp[(size_t)r * Vn + col]       = expf(c[mt][nt][0] + fc2_b[col]);
                g_exp[(size_t)(r + 8) * Vn + col] = expf(c[mt][nt][2] + fc2_b[col]);
            }
            if (col + 1 < Vn) {
                g_exp[(size_t)r * Vn + col + 1]       = expf(c[mt][nt][1] + fc2_b[col + 1]);
                g_exp[(size_t)(r + 8) * Vn + col + 1] = expf(c[mt][nt][3] + fc2_b[col + 1]);
            }
        }
    }
}

// ---------------------------------------------------------------------------
// K4': fc1 GEMM (256 x 1024 x 912), same structure, raw tf32 feed.
// Epilogue: logit + bias -> g_fc1 (fp32).
// ---------------------------------------------------------------------------
__global__ __launch_bounds__(256, 1) void k_fc1g(const float* __restrict__ fc1_w,
                                                 const float* __restrict__ fc1_b) {
    __shared__ float As[2][128][LDP];
    __shared__ float Bs[2][128][LDP];

    int tid = threadIdx.x;
    int bm = blockIdx.y;            // 0..1
    int bn = blockIdx.x;            // 0..7
    int warp = tid >> 5, lane = tid & 31;
    int wm = warp >> 2;
    int wn = warp & 3;
    int nBase = bn * 128;

    float c[4][4][4];
    #pragma unroll
    for (int i = 0; i < 4; i++)
        #pragma unroll
        for (int j = 0; j < 4; j++)
            #pragma unroll
            for (int k = 0; k < 4; k++) c[i][j][k] = 0.f;

    int crow0 = tid >> 2;
    int coff0 = (tid & 3);
    int crow1 = (tid + 256) >> 2;
    int coff1 = ((tid + 256) & 3);

    const float* A = g_din;

    auto issue = [&](int kt, int s) {
        const float* a0 = A + (size_t)(bm * 128 + crow0) * DIN + kt * 16 + coff0 * 4;
        const float* a1 = A + (size_t)(bm * 128 + crow1) * DIN + kt * 16 + coff1 * 4;
        const float* b0 = fc1_w + (size_t)(nBase + crow0) * DIN + kt * 16 + coff0 * 4;
        const float* b1 = fc1_w + (size_t)(nBase + crow1) * DIN + kt * 16 + coff1 * 4;
        unsigned da0 = (unsigned)__cvta_generic_to_shared(&As[s][crow0][coff0 * 4]);
        unsigned da1 = (unsigned)__cvta_generic_to_shared(&As[s][crow1][coff1 * 4]);
        unsigned db0 = (unsigned)__cvta_generic_to_shared(&Bs[s][crow0][coff0 * 4]);
        unsigned db1 = (unsigned)__cvta_generic_to_shared(&Bs[s][crow1][coff1 * 4]);
        CP_ASYNC(da0, a0); CP_ASYNC(da1, a1);
        CP_ASYNC(db0, b0); CP_ASYNC(db1, b1);
        CP_COMMIT();
    };

    issue(0, 0);

    for (int kt = 0; kt < KT1; kt++) {
        int s = kt & 1;
        if (kt + 1 < KT1) {
            issue(kt + 1, s ^ 1);
            CP_WAIT(1);
        } else {
            CP_WAIT(0);
        }
        __syncthreads();

        #pragma unroll
        for (int ks = 0; ks < 2; ks++) {
            unsigned afr[4][4], bfr[4][2];
            int k0 = ks * 8 + (lane & 3);
            #pragma unroll
            for (int mt = 0; mt < 4; mt++) {
                int r0 = wm * 64 + mt * 16 + (lane >> 2);
                afr[mt][0] = __float_as_uint(As[s][r0][k0]);
                afr[mt][1] = __float_as_uint(As[s][r0 + 8][k0]);
                afr[mt][2] = __float_as_uint(As[s][r0][k0 + 4]);
                afr[mt][3] = __float_as_uint(As[s][r0 + 8][k0 + 4]);
            }
            #pragma unroll
            for (int nt = 0; nt < 4; nt++) {
                int n0 = wn * 32 + nt * 8 + (lane >> 2);
                bfr[nt][0] = __float_as_uint(Bs[s][n0][k0]);
                bfr[nt][1] = __float_as_uint(Bs[s][n0][k0 + 4]);
            }
            #pragma unroll
            for (int mt = 0; mt < 4; mt++)
                #pragma unroll
                for (int nt = 0; nt < 4; nt++)
                    mma_tf32(c[mt][nt], afr[mt], bfr[nt]);
        }
        __syncthreads();
    }

    // epilogue: + bias -> g_fc1 (fp32)
    #pragma unroll
    for (int mt = 0; mt < 4; mt++) {
        int r = bm * 128 + wm * 64 + mt * 16 + (lane >> 2);
        #pragma unroll
        for (int nt = 0; nt < 4; nt++) {
            int col = nBase + wn * 32 + nt * 8 + 2 * (lane & 3);
            g_fc1[(size_t)r * H2 + col]           = c[mt][nt][0] + fc1_b[col];
            g_fc1[(size_t)r * H2 + col + 1]       = c[mt][nt][1] + fc1_b[col + 1];
            g_fc1[(size_t)(r + 8) * H2 + col]     = c[mt][nt][2] + fc1_b[col];
            g_fc1[(size_t)(r + 8) * H2 + col + 1] = c[mt][nt][3] + fc1_b[col + 1];
        }
    }
}

// ---------------------------------------------------------------------------
// K7: row sums of g_exp (proven)
// ---------------------------------------------------------------------------
__global__ void k_sum() {
    int b = blockIdx.x;
    __shared__ float red[32];
    const float4* p = (const float4*)(g_exp + (size_t)b * Vn);
    float s = 0.f;
    for (int i = threadIdx.x; i < Vn / 4; i += blockDim.x) {
        float4 q = p[i];
        s += q.x + q.y + q.z + q.w;
    }
    s = block_sum(s, red);
    if (threadIdx.x == 0) g_sum[b] = s;
}

// ---------------------------------------------------------------------------
// K8: finalize (proven)
// ---------------------------------------------------------------------------
__global__ void k_final(float* __restrict__ out) {
    int b = blockIdx.y;
    int v = blockIdx.x * blockDim.x + threadIdx.x;
    if (v >= Pn) return;
    float scale = g_gen[b] / g_sum[b];
    float r = 0.f;
    if (v < Vn) r = scale * g_exp[(size_t)b * Vn + v];
    out[(size_t)b * Pn + v] = r;
}

// ---------------------------------------------------------------------------
// K9: scatter-add (proven)
// ---------------------------------------------------------------------------
__global__ void k_scatter(float* __restrict__ out, const int* __restrict__ ids) {
    int b = blockIdx.x;
    int a = threadIdx.x;
    if (a < An) {
        float w = (1.0f - g_gen[b]) * g_att[b * An + a];
        int id = ids[b * An + a];
        atomicAdd(&out[(size_t)b * Pn + id], w);
    }
}

// ---------------------------------------------------------------------------
extern "C" void kernel_launch(void* const* d_in, const int* in_sizes, int n_in,
                              void* d_out, int out_size) {
    const float* x         = (const float*)d_in[0];
    const float* enc_out   = (const float*)d_in[2];
    const float* enc_state = (const float*)d_in[4];
    const int*   ids       = (const int*)d_in[6];
    const float* W_ih      = (const float*)d_in[7];
    const float* b_ih      = (const float*)d_in[9];
    const float* b_hh      = (const float*)d_in[10];
    const float* Wh_w      = (const float*)d_in[11];
    const float* Wh_b      = (const float*)d_in[12];
    const float* Ws_w      = (const float*)d_in[13];
    const float* Ws_b      = (const float*)d_in[14];
    const float* vvec      = (const float*)d_in[15];
    const float* fc1_w     = (const float*)d_in[16];
    const float* fc1_b     = (const float*)d_in[17];
    const float* fc2_w     = (const float*)d_in[18];
    const float* fc2_b     = (const float*)d_in[19];
    const float* pg1       = (const float*)d_in[20];
    const float* pg2       = (const float*)d_in[21];
    const float* pg3       = (const float*)d_in[22];
    float* out = (float*)d_out;

    k_lstm<<<Bn, 256>>>(x, W_ih, b_ih, b_hh);
    k_attn<<<Bn, 256>>>(enc_state, Wh_w, Wh_b, Ws_w, Ws_b, vvec);
    k_ctx<<<dim3(4, Bn), 416>>>(enc_out);
    k_ctxred<<<Bn, 416>>>();
    k_gen<<<Bn, 256>>>(x, pg1, pg2, pg3);
    k_din<<<Bn, 256>>>();
    k_fc1g<<<dim3(H2 / 128, Bn / 128), 256>>>(fc1_w, fc1_b);
    k_fc2<<<dim3(NBN, Bn / 128), 256>>>(fc2_w, fc2_b);
    k_sum<<<Bn, 1024>>>();
    k_final<<<dim3((Pn + 255) / 256, Bn), 256>>>(out);
    k_scatter<<<Bn, 416>>>(out, ids);
}

// round 8
// speedup vs baseline: 1.5411x; 1.1279x over previous
#include <cuda_runtime.h>
#include <math.h>

// Problem constants
#define Bn   256
#define In   256
#define Hn   512
#define An   400
#define Vn   50000
#define OOVn 50
#define Pn   (Vn + OOVn)      // 50050
#define H2   (2 * Hn)          // 1024
#define DIN  (An + Hn)         // 912 = 57*16
#define NBN  391               // fc2 n-blocks (391*128 = 50048)

// Scratch (static device globals: allocation-free rule)
__device__ float g_h[Bn * Hn];
__device__ float g_att[Bn * An];
__device__ float g_ctxp[4 * Bn * An];
__device__ float g_ctx[Bn * An];
__device__ float g_din[Bn * DIN];
__device__ float g_fc1[Bn * H2];
__device__ float g_gen[Bn];
__device__ float g_sum[Bn];
__device__ float g_exp[(size_t)Bn * Vn];   // 51.2 MB

__device__ __forceinline__ float sigmoidf(float x) { return 1.0f / (1.0f + expf(-x)); }

__device__ __forceinline__ float warp_sum(float v) {
    #pragma unroll
    for (int o = 16; o; o >>= 1) v += __shfl_xor_sync(0xFFFFFFFFu, v, o);
    return v;
}

__device__ __forceinline__ float block_sum(float v, float* red) {
    int lane = threadIdx.x & 31, warp = threadIdx.x >> 5;
    v = warp_sum(v);
    if (lane == 0) red[warp] = v;
    __syncthreads();
    int nw = (blockDim.x + 31) >> 5;
    float r = (threadIdx.x < nw) ? red[threadIdx.x] : 0.0f;
    if (warp == 0) r = warp_sum(r);
    if (threadIdx.x == 0) red[0] = r;
    __syncthreads();
    return red[0];
}

__device__ __forceinline__ float block_max(float v, float* red) {
    int lane = threadIdx.x & 31, warp = threadIdx.x >> 5;
    #pragma unroll
    for (int o = 16; o; o >>= 1) v = fmaxf(v, __shfl_xor_sync(0xFFFFFFFFu, v, o));
    if (lane == 0) red[warp] = v;
    __syncthreads();
    int nw = (blockDim.x + 31) >> 5;
    float r = (threadIdx.x < nw) ? red[threadIdx.x] : -INFINITY;
    if (warp == 0) {
        #pragma unroll
        for (int o = 16; o; o >>= 1) r = fmaxf(r, __shfl_xor_sync(0xFFFFFFFFu, r, o));
    }
    if (threadIdx.x == 0) red[0] = r;
    __syncthreads();
    return red[0];
}

// ---------------------------------------------------------------------------
// K1: degenerate LSTM cell (proven)
// ---------------------------------------------------------------------------
__global__ void k_lstm(const float* __restrict__ x, const float* __restrict__ W_ih,
                       const float* __restrict__ b_ih, const float* __restrict__ b_hh) {
    int b = blockIdx.x;
    __shared__ float sx[In];
    for (int i = threadIdx.x; i < In; i += blockDim.x) sx[i] = x[b * In + i];
    __syncthreads();
    int warp = threadIdx.x >> 5, lane = threadIdx.x & 31;
    for (int j = warp; j < Hn; j += (blockDim.x >> 5)) {
        const float* wi = W_ih + (size_t)j * In;
        const float* wg = W_ih + (size_t)(2 * Hn + j) * In;
        const float* wo = W_ih + (size_t)(3 * Hn + j) * In;
        float ai = 0.f, ag = 0.f, ao = 0.f;
        for (int k = lane; k < In; k += 32) {
            float xv = sx[k];
            ai = fmaf(xv, wi[k], ai);
            ag = fmaf(xv, wg[k], ag);
            ao = fmaf(xv, wo[k], ao);
        }
        ai = warp_sum(ai); ag = warp_sum(ag); ao = warp_sum(ao);
        if (lane == 0) {
            ai += b_ih[j] + b_hh[j];
            ag += b_ih[2 * Hn + j] + b_hh[2 * Hn + j];
            ao += b_ih[3 * Hn + j] + b_hh[3 * Hn + j];
            float c = sigmoidf(ai) * tanhf(ag);
            g_h[b * Hn + j] = sigmoidf(ao) * tanhf(c);
        }
    }
}

// ---------------------------------------------------------------------------
// K2: attention (proven)
// ---------------------------------------------------------------------------
__global__ void k_attn(const float* __restrict__ enc_state,
                       const float* __restrict__ Wh_w, const float* __restrict__ Wh_b,
                       const float* __restrict__ Ws_w, const float* __restrict__ Ws_b,
                       const float* __restrict__ vvec) {
    int b = blockIdx.x;
    __shared__ float ss[Hn], sh[Hn], se[An], red[32];
    for (int i = threadIdx.x; i < Hn; i += blockDim.x) {
        ss[i] = enc_state[b * Hn + i];
        sh[i] = g_h[b * Hn + i];
    }
    __syncthreads();
    int warp = threadIdx.x >> 5, lane = threadIdx.x & 31;
    for (int a = warp; a < An; a += (blockDim.x >> 5)) {
        const float* w1 = Wh_w + (size_t)a * Hn;
        const float* w2 = Ws_w + (size_t)a * Hn;
        float acc = 0.f;
        for (int k = lane; k < Hn; k += 32)
            acc = fmaf(ss[k], w1[k], fmaf(sh[k], w2[k], acc));
        acc = warp_sum(acc);
        if (lane == 0) se[a] = tanhf(acc + Wh_b[a] + Ws_b[a]);
    }
    __syncthreads();
    float m = -INFINITY;
    for (int i = threadIdx.x; i < An; i += blockDim.x) m = fmaxf(m, se[i]);
    m = block_max(m, red);
    float s = 0.f;
    for (int i = threadIdx.x; i < An; i += blockDim.x) s += expf(se[i] - m);
    s = block_sum(s, red);
    float inv = 1.0f / s;
    for (int i = threadIdx.x; i < An; i += blockDim.x)
        g_att[b * An + i] = vvec[i] * expf(se[i] - m) * inv;
}

// ---------------------------------------------------------------------------
// K3: context partials (proven scalar version)
// ---------------------------------------------------------------------------
__global__ void k_ctx(const float* __restrict__ enc_out) {
    int slice = blockIdx.x;     // 0..3
    int b = blockIdx.y;         // 0..255
    int a0 = slice * 100;
    __shared__ float sa[100];
    if (threadIdx.x < 100) sa[threadIdx.x] = g_att[b * An + a0 + threadIdx.x];
    __syncthreads();
    int e = threadIdx.x;
    if (e < An) {
        const float* base = enc_out + ((size_t)b * An + a0) * An + e;
        float acc = 0.f;
        #pragma unroll 5
        for (int i = 0; i < 100; i++) acc = fmaf(sa[i], base[(size_t)i * An], acc);
        g_ctxp[((size_t)slice * Bn + b) * An + e] = acc;
    }
}

__global__ void k_ctxred() {
    int b = blockIdx.x;
    int e = threadIdx.x;
    if (e < An) {
        float s = g_ctxp[((size_t)0 * Bn + b) * An + e]
                + g_ctxp[((size_t)1 * Bn + b) * An + e]
                + g_ctxp[((size_t)2 * Bn + b) * An + e]
                + g_ctxp[((size_t)3 * Bn + b) * An + e];
        g_ctx[b * An + e] = s;
    }
}

// ---------------------------------------------------------------------------
// K5: gen gate (proven) + dec_in assembly (also zeroes g_sum for fused rowsum)
// ---------------------------------------------------------------------------
__global__ void k_gen(const float* __restrict__ x, const float* __restrict__ pg1,
                      const float* __restrict__ pg2, const float* __restrict__ pg3) {
    int b = blockIdx.x;
    __shared__ float red[32];
    float acc = 0.f;
    for (int k = threadIdx.x; k < In; k += blockDim.x) acc = fmaf(x[b * In + k], pg1[k], acc);
    for (int k = threadIdx.x; k < An; k += blockDim.x) acc = fmaf(g_ctx[b * An + k], pg2[k], acc);
    for (int k = threadIdx.x; k < Hn; k += blockDim.x) acc = fmaf(g_h[b * Hn + k], pg3[k], acc);
    acc = block_sum(acc, red);
    if (threadIdx.x == 0) g_gen[b] = sigmoidf(acc);
}

__global__ void k_din() {
    int b = blockIdx.x;
    if (threadIdx.x == 0) g_sum[b] = 0.0f;   // zero for fc2's fused atomic rowsum
    for (int i = threadIdx.x; i < DIN; i += blockDim.x) {
        float v = (i < An) ? g_ctx[b * An + i] : g_h[b * Hn + (i - An)];
        g_din[b * DIN + i] = v;
    }
}

// ---------------------------------------------------------------------------
// tf32 MMA machinery (raw fp32 bits fed to tf32 MMA: HW truncation, no CVT)
// ---------------------------------------------------------------------------
#define CP_ASYNC(dst, src)        asm volatile("cp.async.cg.shared.global [%0], [%1], 16;" :: "r"(dst), "l"(src))
#define CP_ASYNC_Z(dst, src, sz)  asm volatile("cp.async.cg.shared.global [%0], [%1], 16, %2;" :: "r"(dst), "l"(src), "r"(sz))
#define CP_COMMIT()               asm volatile("cp.async.commit_group;")
#define CP_WAIT(n)                asm volatile("cp.async.wait_group %0;" :: "n"(n))

__device__ __forceinline__ void mma_tf32(float c[4], const unsigned a[4], const unsigned b[2]) {
    asm volatile(
        "mma.sync.aligned.m16n8k8.row.col.f32.tf32.tf32.f32 "
        "{%0,%1,%2,%3}, {%4,%5,%6,%7}, {%8,%9}, {%0,%1,%2,%3};"
        : "+f"(c[0]), "+f"(c[1]), "+f"(c[2]), "+f"(c[3])
        : "r"(a[0]), "r"(a[1]), "r"(a[2]), "r"(a[3]), "r"(b[0]), "r"(b[1]));
}

#define LDP 20   // float pitch per smem row (16 data + 4 pad) — conflict-free frag loads
#define KT2 (H2 / 16)    // 64 k-tiles for fc2
#define KT1 (DIN / 16)   // 57 k-tiles for fc1

// ---------------------------------------------------------------------------
// K6: fc2 GEMM (256 x 50000 x 1024), 128 threads / 4 warps (2x2), warp tile
// 64x64, cp.async double-buffered, raw tf32 feed.
// Epilogue: exp(logit + bias) -> g_exp + fused atomic row-sums into g_sum.
// ---------------------------------------------------------------------------
__global__ __launch_bounds__(128) void k_fc2(const float* __restrict__ fc2_w,
                                             const float* __restrict__ fc2_b) {
    __shared__ float As[2][128][LDP];
    __shared__ float Bs[2][128][LDP];

    int tid = threadIdx.x;
    int bm = blockIdx.y;            // 0..1
    int bn = blockIdx.x;            // 0..390
    int warp = tid >> 5, lane = tid & 31;
    int wm = warp >> 1;             // 0..1 -> row offset wm*64
    int wn = warp & 1;              // 0..1 -> col offset wn*64
    int nBase = bn * 128;

    float c[4][8][4];
    #pragma unroll
    for (int i = 0; i < 4; i++)
        #pragma unroll
        for (int j = 0; j < 8; j++)
            #pragma unroll
            for (int k = 0; k < 4; k++) c[i][j][k] = 0.f;

    // copy map: 128 rows x 4 chunks of 16B each for A and B = 1024 chunks; 8/thread
    int crow[4], coff[4], bok[4];
    #pragma unroll
    for (int p = 0; p < 4; p++) {
        int ch = tid + p * 128;
        crow[p] = ch >> 2;
        coff[p] = (ch & 3) * 4;
        bok[p] = (nBase + crow[p] < Vn) ? 16 : 0;
    }

    const float* A = g_fc1;

    auto issue = [&](int kt, int s) {
        #pragma unroll
        for (int p = 0; p < 4; p++) {
            const float* a0 = A + (size_t)(bm * 128 + crow[p]) * H2 + kt * 16 + coff[p];
            unsigned da = (unsigned)__cvta_generic_to_shared(&As[s][crow[p]][coff[p]]);
            CP_ASYNC(da, a0);
        }
        #pragma unroll
        for (int p = 0; p < 4; p++) {
            const float* b0 = fc2_w + (size_t)(nBase + crow[p]) * H2 + kt * 16 + coff[p];
            unsigned db = (unsigned)__cvta_generic_to_shared(&Bs[s][crow[p]][coff[p]]);
            CP_ASYNC_Z(db, b0, bok[p]);
        }
        CP_COMMIT();
    };

    issue(0, 0);

    for (int kt = 0; kt < KT2; kt++) {
        int s = kt & 1;
        if (kt + 1 < KT2) {
            issue(kt + 1, s ^ 1);
            CP_WAIT(1);
        } else {
            CP_WAIT(0);
        }
        __syncthreads();

        #pragma unroll
        for (int ks = 0; ks < 2; ks++) {
            unsigned afr[4][4], bfr[8][2];
            int k0 = ks * 8 + (lane & 3);
            #pragma unroll
            for (int mt = 0; mt < 4; mt++) {
                int r0 = wm * 64 + mt * 16 + (lane >> 2);
                afr[mt][0] = __float_as_uint(As[s][r0][k0]);
                afr[mt][1] = __float_as_uint(As[s][r0 + 8][k0]);
                afr[mt][2] = __float_as_uint(As[s][r0][k0 + 4]);
                afr[mt][3] = __float_as_uint(As[s][r0 + 8][k0 + 4]);
            }
            #pragma unroll
            for (int nt = 0; nt < 8; nt++) {
                int n0 = wn * 64 + nt * 8 + (lane >> 2);
                bfr[nt][0] = __float_as_uint(Bs[s][n0][k0]);
                bfr[nt][1] = __float_as_uint(Bs[s][n0][k0 + 4]);
            }
            #pragma unroll
            for (int mt = 0; mt < 4; mt++)
                #pragma unroll
                for (int nt = 0; nt < 8; nt++)
                    mma_tf32(c[mt][nt], afr[mt], bfr[nt]);
        }
        __syncthreads();
    }

    // epilogue: exp(logit + bias) -> g_exp, plus fused row sums -> g_sum (atomic)
    #pragma unroll
    for (int mt = 0; mt < 4; mt++) {
        int r = bm * 128 + wm * 64 + mt * 16 + (lane >> 2);
        float rs0 = 0.f, rs1 = 0.f;
        #pragma unroll
        for (int nt = 0; nt < 8; nt++) {
            int col = nBase + wn * 64 + nt * 8 + 2 * (lane & 3);
            if (col < Vn) {
                float e0 = expf(c[mt][nt][0] + fc2_b[col]);
                float e2 = expf(c[mt][nt][2] + fc2_b[col]);
                g_exp[(size_t)r * Vn + col]       = e0;
                g_exp[(size_t)(r + 8) * Vn + col] = e2;
                rs0 += e0; rs1 += e2;
            }
            if (col + 1 < Vn) {
                float e1 = expf(c[mt][nt][1] + fc2_b[col + 1]);
                float e3 = expf(c[mt][nt][3] + fc2_b[col + 1]);
                g_exp[(size_t)r * Vn + col + 1]       = e1;
                g_exp[(size_t)(r + 8) * Vn + col + 1] = e3;
                rs0 += e1; rs1 += e3;
            }
        }
        // reduce over the 4 lanes sharing the same rows (lane>>2 groups)
        rs0 += __shfl_xor_sync(0xFFFFFFFFu, rs0, 1);
        rs0 += __shfl_xor_sync(0xFFFFFFFFu, rs0, 2);
        rs1 += __shfl_xor_sync(0xFFFFFFFFu, rs1, 1);
        rs1 += __shfl_xor_sync(0xFFFFFFFFu, rs1, 2);
        if ((lane & 3) == 0) {
            atomicAdd(&g_sum[r], rs0);
            atomicAdd(&g_sum[r + 8], rs1);
        }
    }
}

// ---------------------------------------------------------------------------
// K4': fc1 GEMM (256 x 1024 x 912), proven R7 version (256 threads).
// ---------------------------------------------------------------------------
__global__ __launch_bounds__(256, 1) void k_fc1g(const float* __restrict__ fc1_w,
                                                 const float* __restrict__ fc1_b) {
    __shared__ float As[2][128][LDP];
    __shared__ float Bs[2][128][LDP];

    int tid = threadIdx.x;
    int bm = blockIdx.y;            // 0..1
    int bn = blockIdx.x;            // 0..7
    int warp = tid >> 5, lane = tid & 31;
    int wm = warp >> 2;
    int wn = warp & 3;
    int nBase = bn * 128;

    float c[4][4][4];
    #pragma unroll
    for (int i = 0; i < 4; i++)
        #pragma unroll
        for (int j = 0; j < 4; j++)
            #pragma unroll
            for (int k = 0; k < 4; k++) c[i][j][k] = 0.f;

    int crow0 = tid >> 2;
    int coff0 = (tid & 3);
    int crow1 = (tid + 256) >> 2;
    int coff1 = ((tid + 256) & 3);

    const float* A = g_din;

    auto issue = [&](int kt, int s) {
        const float* a0 = A + (size_t)(bm * 128 + crow0) * DIN + kt * 16 + coff0 * 4;
        const float* a1 = A + (size_t)(bm * 128 + crow1) * DIN + kt * 16 + coff1 * 4;
        const float* b0 = fc1_w + (size_t)(nBase + crow0) * DIN + kt * 16 + coff0 * 4;
        const float* b1 = fc1_w + (size_t)(nBase + crow1) * DIN + kt * 16 + coff1 * 4;
        unsigned da0 = (unsigned)__cvta_generic_to_shared(&As[s][crow0][coff0 * 4]);
        unsigned da1 = (unsigned)__cvta_generic_to_shared(&As[s][crow1][coff1 * 4]);
        unsigned db0 = (unsigned)__cvta_generic_to_shared(&Bs[s][crow0][coff0 * 4]);
        unsigned db1 = (unsigned)__cvta_generic_to_shared(&Bs[s][crow1][coff1 * 4]);
        CP_ASYNC(da0, a0); CP_ASYNC(da1, a1);
        CP_ASYNC(db0, b0); CP_ASYNC(db1, b1);
        CP_COMMIT();
    };

    issue(0, 0);

    for (int kt = 0; kt < KT1; kt++) {
        int s = kt & 1;
        if (kt + 1 < KT1) {
            issue(kt + 1, s ^ 1);
            CP_WAIT(1);
        } else {
            CP_WAIT(0);
        }
        __syncthreads();

        #pragma unroll
        for (int ks = 0; ks < 2; ks++) {
            unsigned afr[4][4], bfr[4][2];
            int k0 = ks * 8 + (lane & 3);
            #pragma unroll
            for (int mt = 0; mt < 4; mt++) {
                int r0 = wm * 64 + mt * 16 + (lane >> 2);
                afr[mt][0] = __float_as_uint(As[s][r0][k0]);
                afr[mt][1] = __float_as_uint(As[s][r0 + 8][k0]);
                afr[mt][2] = __float_as_uint(As[s][r0][k0 + 4]);
                afr[mt][3] = __float_as_uint(As[s][r0 + 8][k0 + 4]);
            }
            #pragma unroll
            for (int nt = 0; nt < 4; nt++) {
                int n0 = wn * 32 + nt * 8 + (lane >> 2);
                bfr[nt][0] = __float_as_uint(Bs[s][n0][k0]);
                bfr[nt][1] = __float_as_uint(Bs[s][n0][k0 + 4]);
            }
            #pragma unroll
            for (int mt = 0; mt < 4; mt++)
                #pragma unroll
                for (int nt = 0; nt < 4; nt++)
                    mma_tf32(c[mt][nt], afr[mt], bfr[nt]);
        }
        __syncthreads();
    }

    #pragma unroll
    for (int mt = 0; mt < 4; mt++) {
        int r = bm * 128 + wm * 64 + mt * 16 + (lane >> 2);
        #pragma unroll
        for (int nt = 0; nt < 4; nt++) {
            int col = nBase + wn * 32 + nt * 8 + 2 * (lane & 3);
            g_fc1[(size_t)r * H2 + col]           = c[mt][nt][0] + fc1_b[col];
            g_fc1[(size_t)r * H2 + col + 1]       = c[mt][nt][1] + fc1_b[col + 1];
            g_fc1[(size_t)(r + 8) * H2 + col]     = c[mt][nt][2] + fc1_b[col];
            g_fc1[(size_t)(r + 8) * H2 + col + 1] = c[mt][nt][3] + fc1_b[col + 1];
        }
    }
}

// ---------------------------------------------------------------------------
// K8: finalize (proven)
// ---------------------------------------------------------------------------
__global__ void k_final(float* __restrict__ out) {
    int b = blockIdx.y;
    int v = blockIdx.x * blockDim.x + threadIdx.x;
    if (v >= Pn) return;
    float scale = g_gen[b] / g_sum[b];
    float r = 0.f;
    if (v < Vn) r = scale * g_exp[(size_t)b * Vn + v];
    out[(size_t)b * Pn + v] = r;
}

// ---------------------------------------------------------------------------
// K9: scatter-add (proven)
// ---------------------------------------------------------------------------
__global__ void k_scatter(float* __restrict__ out, const int* __restrict__ ids) {
    int b = blockIdx.x;
    int a = threadIdx.x;
    if (a < An) {
        float w = (1.0f - g_gen[b]) * g_att[b * An + a];
        int id = ids[b * An + a];
        atomicAdd(&out[(size_t)b * Pn + id], w);
    }
}

// ---------------------------------------------------------------------------
extern "C" void kernel_launch(void* const* d_in, const int* in_sizes, int n_in,
                              void* d_out, int out_size) {
    const float* x         = (const float*)d_in[0];
    const float* enc_out   = (const float*)d_in[2];
    const float* enc_state = (const float*)d_in[4];
    const int*   ids       = (const int*)d_in[6];
    const float* W_ih      = (const float*)d_in[7];
    const float* b_ih      = (const float*)d_in[9];
    const float* b_hh      = (const float*)d_in[10];
    const float* Wh_w      = (const float*)d_in[11];
    const float* Wh_b      = (const float*)d_in[12];
    const float* Ws_w      = (const float*)d_in[13];
    const float* Ws_b      = (const float*)d_in[14];
    const float* vvec      = (const float*)d_in[15];
    const float* fc1_w     = (const float*)d_in[16];
    const float* fc1_b     = (const float*)d_in[17];
    const float* fc2_w     = (const float*)d_in[18];
    const float* fc2_b     = (const float*)d_in[19];
    const float* pg1       = (const float*)d_in[20];
    const float* pg2       = (const float*)d_in[21];
    const float* pg3       = (const float*)d_in[22];
    float* out = (float*)d_out;

    k_lstm<<<Bn, 256>>>(x, W_ih, b_ih, b_hh);
    k_attn<<<Bn, 256>>>(enc_state, Wh_w, Wh_b, Ws_w, Ws_b, vvec);
    k_ctx<<<dim3(4, Bn), 416>>>(enc_out);
    k_ctxred<<<Bn, 416>>>();
    k_gen<<<Bn, 256>>>(x, pg1, pg2, pg3);
    k_din<<<Bn, 256>>>();
    k_fc1g<<<dim3(H2 / 128, Bn / 128), 256>>>(fc1_w, fc1_b);
    k_fc2<<<dim3(NBN, Bn / 128), 128>>>(fc2_w, fc2_b);
    k_final<<<dim3((Pn + 255) / 256, Bn), 256>>>(out);
    k_scatter<<<Bn, 416>>>(out, ids);
}